// round 8
// baseline (speedup 1.0000x reference)
#include <cuda_runtime.h>
#include <cstdint>
#include <cstddef>

static constexpr int NN = 50000;   // nodes
static constexpr int NE = 800000;  // edges
// features: 128 -> 256 -> 128

// ---------------- scratch (device globals; no allocation allowed) -----------
__device__ int   g_is64;                     // edge_index dtype flag
__device__ int   g_cnt[NN];                  // in-degree (no self-loop)
__device__ int   g_cur[NN];                  // fill cursors
__device__ int   g_row[NN];                  // CSR row starts
__device__ int   g_csr[NE];                  // CSR src indices
__device__ float g_nrm[NE];                  // per-edge norm isd[s]*isd[d]
__device__ float g_isd[NN];                  // 1/sqrt(deg), deg incl self-loop
__device__ float g_ax[(size_t)NN * 128];     // A_norm @ x
__device__ float g_z1[(size_t)NN * 256];     // relu(ax @ W1 + b1)
__device__ float g_t2[(size_t)NN * 128];     // z1 @ W2

// ---------------- setup: dtype probe + zero init + out init ------------------
__global__ void k_setup(const void* __restrict__ ei,
                        const float* __restrict__ bfc,
                        float* __restrict__ out) {
    int i = blockIdx.x * blockDim.x + threadIdx.x;
    if (i < NN) { g_cnt[i] = 0; g_cur[i] = 0; }
    if (i == 0) out[0] = bfc[0];

    if (blockIdx.x == 0) {
        // dtype probe: read first 1024 entries as int64 (8 KB, safe in either
        // dtype's buffer). All in [0, NN) => int64, else int32.
        __shared__ int bad;
        if (threadIdx.x == 0) bad = 0;
        __syncthreads();
        const long long* p = (const long long*)ei;
        for (int k = threadIdx.x; k < 1024; k += blockDim.x) {
            long long v = p[k];
            if (v < 0 || v >= NN) bad = 1;
        }
        __syncthreads();
        if (threadIdx.x == 0) g_is64 = bad ? 0 : 1;
    }
}

__device__ __forceinline__ int edge_at(const void* __restrict__ ei, int idx) {
    if (g_is64) return (int)((const long long*)ei)[idx];
    return ((const int*)ei)[idx];
}

// ---------------- degree count ----------------------------------------------
__global__ void k_count(const void* __restrict__ ei) {
    int e = blockIdx.x * blockDim.x + threadIdx.x;
    if (e < NE) atomicAdd(&g_cnt[edge_at(ei, NE + e)], 1);
}

// ---------------- scan (row starts) + isd ------------------------------------
__global__ void __launch_bounds__(1024) k_scan() {
    __shared__ int sh[2][1024];
    const int t  = threadIdx.x;
    const int CH = (NN + 1023) / 1024;   // 49
    const int b0 = t * CH;

    int local = 0;
    for (int i = 0; i < CH; i++) {
        int idx = b0 + i;
        if (idx < NN) local += g_cnt[idx];
    }
    int cur = 0;
    sh[cur][t] = local;
    __syncthreads();
    for (int off = 1; off < 1024; off <<= 1) {
        int nxt = cur ^ 1;
        int v = sh[cur][t];
        if (t >= off) v += sh[cur][t - off];
        sh[nxt][t] = v;
        __syncthreads();
        cur = nxt;
    }
    int run = (t == 0) ? 0 : sh[cur][t - 1];
    for (int i = 0; i < CH; i++) {
        int idx = b0 + i;
        if (idx < NN) {
            int c = g_cnt[idx];
            g_row[idx] = run;
            g_isd[idx] = rsqrtf(1.0f + (float)c);
            run += c;
        }
    }
}

// fill CSR with src index + precomputed edge norm isd[s]*isd[d]
__global__ void k_fill(const void* __restrict__ ei) {
    int e = blockIdx.x * blockDim.x + threadIdx.x;
    if (e >= NE) return;
    int s = edge_at(ei, e);
    int d = edge_at(ei, NE + e);
    int pos = g_row[d] + atomicAdd(&g_cur[d], 1);
    g_csr[pos] = s;
    g_nrm[pos] = g_isd[s] * g_isd[d];
}

// ---------------- gather core: acc += sum over in-edges of nrm[e] * h[src] ---
// Uniform scalar loads (warp-broadcast), 4-way unrolled for MLP; norm is
// precomputed so there is no dependent isd lookup on the critical path.
__device__ __forceinline__ float4 gather_rows(const float* __restrict__ h,
                                              int node, int lane, float4 acc) {
    const int beg = g_row[node];
    const int end = beg + g_cnt[node];
    int e = beg;
    for (; e + 4 <= end; e += 4) {
        int   s0 = g_csr[e];     int   s1 = g_csr[e + 1];
        int   s2 = g_csr[e + 2]; int   s3 = g_csr[e + 3];
        float n0 = g_nrm[e];     float n1 = g_nrm[e + 1];
        float n2 = g_nrm[e + 2]; float n3 = g_nrm[e + 3];
        float4 a = ((const float4*)(h + (size_t)s0 * 128))[lane];
        float4 b = ((const float4*)(h + (size_t)s1 * 128))[lane];
        float4 c = ((const float4*)(h + (size_t)s2 * 128))[lane];
        float4 d = ((const float4*)(h + (size_t)s3 * 128))[lane];
        acc.x += a.x * n0 + b.x * n1 + c.x * n2 + d.x * n3;
        acc.y += a.y * n0 + b.y * n1 + c.y * n2 + d.y * n3;
        acc.z += a.z * n0 + b.z * n1 + c.z * n2 + d.z * n3;
        acc.w += a.w * n0 + b.w * n1 + c.w * n2 + d.w * n3;
    }
    for (; e < end; e++) {
        int   s0 = g_csr[e];
        float n0 = g_nrm[e];
        float4 a = ((const float4*)(h + (size_t)s0 * 128))[lane];
        acc.x += a.x * n0; acc.y += a.y * n0;
        acc.z += a.z * n0; acc.w += a.w * n0;
    }
    return acc;
}

// ---------------- aggregation 1: ax = A_norm @ x (128 feat) ------------------
__global__ void __launch_bounds__(256)
k_aggX(const float* __restrict__ x) {
    const int warp = threadIdx.x >> 5;
    const int lane = threadIdx.x & 31;
    const int node = blockIdx.x * 8 + warp;
    if (node >= NN) return;

    const float sd = g_isd[node];
    float4 t = ((const float4*)(x + (size_t)node * 128))[lane];
    const float w = sd * sd;
    float4 acc = make_float4(t.x * w, t.y * w, t.z * w, t.w * w);

    acc = gather_rows(x, node, lane, acc);

    ((float4*)(g_ax + (size_t)node * 128))[lane] = acc;
}

// ---------------- tf32 tensor-core GEMM --------------------------------------
__device__ __forceinline__ uint32_t f2tf32(float f) {
    uint32_t o;
    asm("cvt.rna.tf32.f32 %0, %1;" : "=r"(o) : "f"(f));
    return o;
}

__device__ __forceinline__ void mma_tf32(float c[4], const uint32_t a[4],
                                         const uint32_t b[2]) {
    asm volatile(
        "mma.sync.aligned.m16n8k8.row.col.f32.tf32.tf32.f32 "
        "{%0,%1,%2,%3}, {%4,%5,%6,%7}, {%8,%9}, {%0,%1,%2,%3};"
        : "+f"(c[0]), "+f"(c[1]), "+f"(c[2]), "+f"(c[3])
        : "r"(a[0]), "r"(a[1]), "r"(a[2]), "r"(a[3]),
          "r"(b[0]), "r"(b[1]));
}

template <bool L1>
__global__ void __launch_bounds__(256)
tgemm(const float* __restrict__ W, const float* __restrict__ bias) {
    constexpr int K   = L1 ? 128 : 256;
    constexpr int N   = L1 ? 256 : 128;
    constexpr int BM  = 128, BN = 64, BK = 32;
    constexpr int LDA = BK + 4;
    constexpr int LDB = BN + 8;
    constexpr int KT  = K / BK;

    const float* __restrict__ A = L1 ? g_ax : g_z1;
    float* __restrict__       C = L1 ? g_z1 : g_t2;

    __shared__ uint32_t As[BM * LDA];
    __shared__ uint32_t Bs[BK * LDB];

    const int tid  = threadIdx.x;
    const int lane = tid & 31;
    const int wid  = tid >> 5;
    const int wm   = wid & 3;
    const int wn   = wid >> 2;
    const int gID  = lane >> 2;
    const int tg   = lane & 3;

    const int bm0 = blockIdx.y * BM;
    const int bn0 = blockIdx.x * BN;

    float c[2][4][4] = {};

    for (int kt = 0; kt < KT; kt++) {
        #pragma unroll
        for (int i = 0; i < 4; i++) {
            int idx = tid + i * 256;
            int r   = idx >> 3;
            int c4  = (idx & 7) * 4;
            int rg  = bm0 + r;
            float4 v = make_float4(0.f, 0.f, 0.f, 0.f);
            if (rg < NN)
                v = *(const float4*)(A + (size_t)rg * K + kt * BK + c4);
            uint32_t* d = &As[r * LDA + c4];
            d[0] = f2tf32(v.x); d[1] = f2tf32(v.y);
            d[2] = f2tf32(v.z); d[3] = f2tf32(v.w);
        }
        #pragma unroll
        for (int i = 0; i < 2; i++) {
            int idx = tid + i * 256;
            int r   = idx >> 4;
            int c4  = (idx & 15) * 4;
            float4 v = *(const float4*)(W + (size_t)(kt * BK + r) * N + bn0 + c4);
            uint32_t* d = &Bs[r * LDB + c4];
            d[0] = f2tf32(v.x); d[1] = f2tf32(v.y);
            d[2] = f2tf32(v.z); d[3] = f2tf32(v.w);
        }
        __syncthreads();

        #pragma unroll
        for (int kk = 0; kk < BK / 8; kk++) {
            uint32_t a[2][4], b[4][2];
            #pragma unroll
            for (int mi = 0; mi < 2; mi++) {
                int rb = wm * 32 + mi * 16 + gID;
                int kb = kk * 8 + tg;
                a[mi][0] = As[rb * LDA + kb];
                a[mi][1] = As[(rb + 8) * LDA + kb];
                a[mi][2] = As[rb * LDA + kb + 4];
                a[mi][3] = As[(rb + 8) * LDA + kb + 4];
            }
            #pragma unroll
            for (int ni = 0; ni < 4; ni++) {
                int col = wn * 32 + ni * 8 + gID;
                int kb  = kk * 8 + tg;
                b[ni][0] = Bs[kb * LDB + col];
                b[ni][1] = Bs[(kb + 4) * LDB + col];
            }
            #pragma unroll
            for (int mi = 0; mi < 2; mi++)
                #pragma unroll
                for (int ni = 0; ni < 4; ni++)
                    mma_tf32(c[mi][ni], a[mi], b[ni]);
        }
        __syncthreads();
    }

    #pragma unroll
    for (int mi = 0; mi < 2; mi++) {
        int r0 = bm0 + wm * 32 + mi * 16 + gID;
        #pragma unroll
        for (int ni = 0; ni < 4; ni++) {
            int col = bn0 + wn * 32 + ni * 8 + tg * 2;
            float2 v0 = make_float2(c[mi][ni][0], c[mi][ni][1]);
            float2 v1 = make_float2(c[mi][ni][2], c[mi][ni][3]);
            if (L1) {
                float bx = bias[col], by = bias[col + 1];
                v0.x = fmaxf(v0.x + bx, 0.f); v0.y = fmaxf(v0.y + by, 0.f);
                v1.x = fmaxf(v1.x + bx, 0.f); v1.y = fmaxf(v1.y + by, 0.f);
            }
            if (r0 < NN)     *(float2*)(C + (size_t)r0 * N + col) = v0;
            if (r0 + 8 < NN) *(float2*)(C + (size_t)(r0 + 8) * N + col) = v1;
        }
    }
}

// ---------------- aggregation 2 + bias + relu + pool + fc --------------------
__global__ void __launch_bounds__(256)
k_agg2(const float* __restrict__ bias, const float* __restrict__ Wfc,
       float* __restrict__ out) {
    const int warp = threadIdx.x >> 5;
    const int lane = threadIdx.x & 31;
    const int node = blockIdx.x * 8 + warp;
    if (node >= NN) return;

    const float* __restrict__ h = g_t2;
    const float sd = g_isd[node];
    float4 t = ((const float4*)(h + (size_t)node * 128))[lane];
    const float w = sd * sd;
    float4 acc = make_float4(t.x * w, t.y * w, t.z * w, t.w * w);

    acc = gather_rows(h, node, lane, acc);

    float4 bb = ((const float4*)bias)[lane];
    float4 wf = ((const float4*)Wfc)[lane];
    float dot =
        fmaxf(acc.x + bb.x, 0.f) * wf.x +
        fmaxf(acc.y + bb.y, 0.f) * wf.y +
        fmaxf(acc.z + bb.z, 0.f) * wf.z +
        fmaxf(acc.w + bb.w, 0.f) * wf.w;

    #pragma unroll
    for (int o = 16; o; o >>= 1) dot += __shfl_down_sync(0xffffffffu, dot, o);
    if (lane == 0) atomicAdd(out, dot * (1.0f / NN));
}

// ---------------- launch ------------------------------------------------------
extern "C" void kernel_launch(void* const* d_in, const int* in_sizes, int n_in,
                              void* d_out, int out_size) {
    const float* x   = (const float*)d_in[0];
    const void*  ei  = d_in[1];                 // int32 or int64 — probed on device
    const float* W1  = (const float*)d_in[2];
    const float* b1  = (const float*)d_in[3];
    const float* W2  = (const float*)d_in[4];
    const float* b2  = (const float*)d_in[5];
    const float* Wfc = (const float*)d_in[6];
    const float* bfc = (const float*)d_in[7];
    float* out = (float*)d_out;
    (void)in_sizes; (void)n_in; (void)out_size;

    // setup + CSR build
    k_setup<<<(NN + 255) / 256, 256>>>(ei, bfc, out);
    k_count<<<(NE + 255) / 256, 256>>>(ei);
    k_scan <<<1, 1024>>>();
    k_fill <<<(NE + 255) / 256, 256>>>(ei);

    // layer 1: aggregate x first (narrower), then fused GEMM+bias+relu
    k_aggX<<<(NN + 7) / 8, 256>>>(x);
    tgemm<true><<<dim3(256 / 64, (NN + 127) / 128), 256>>>(W1, b1);

    // layer 2: transform first, then fused agg+bias+relu+pool+fc
    tgemm<false><<<dim3(128 / 64, (NN + 127) / 128), 256>>>(W2, nullptr);
    k_agg2<<<(NN + 7) / 8, 256>>>(b2, Wfc, out);
}

// round 11
// speedup vs baseline: 1.1984x; 1.1984x over previous
#include <cuda_runtime.h>
#include <cstdint>
#include <cstddef>

static constexpr int NN = 50000;   // nodes
static constexpr int NE = 800000;  // edges
// features: 128 -> 256 -> 128

// ---------------- scratch (device globals; no allocation allowed) -----------
__device__ int   g_is64;                     // edge_index dtype flag
__device__ int   g_cnt[NN];                  // in-degree (no self-loop)
__device__ int   g_cur[NN];                  // fill cursors
__device__ int   g_row[NN];                  // CSR row starts
__device__ int   g_csr[NE];                  // CSR src indices
__device__ float g_isd[NN];                  // 1/sqrt(deg), deg incl self-loop
__device__ float g_ax[(size_t)NN * 128];     // A_norm @ x
__device__ float g_z1[(size_t)NN * 256];     // relu(ax @ W1 + b1)
__device__ float g_t2[(size_t)NN * 128];     // z1 @ W2

// ---------------- edge_index dtype probe -------------------------------------
__global__ void k_detect(const void* __restrict__ ei) {
    __shared__ int bad;
    if (threadIdx.x == 0) bad = 0;
    __syncthreads();
    const long long* p = (const long long*)ei;
    for (int i = threadIdx.x; i < 1024; i += blockDim.x) {
        long long v = p[i];
        if (v < 0 || v >= NN) bad = 1;
    }
    __syncthreads();
    if (threadIdx.x == 0) g_is64 = bad ? 0 : 1;
}

__device__ __forceinline__ int edge_at(const void* __restrict__ ei, int idx) {
    if (g_is64) return (int)((const long long*)ei)[idx];
    return ((const int*)ei)[idx];
}

// ---------------- degree / CSR build ----------------------------------------
__global__ void k_init() {
    int i = blockIdx.x * blockDim.x + threadIdx.x;
    if (i < NN) { g_cnt[i] = 0; g_cur[i] = 0; }
}

__global__ void k_count(const void* __restrict__ ei) {
    int e = blockIdx.x * blockDim.x + threadIdx.x;
    if (e < NE) atomicAdd(&g_cnt[edge_at(ei, NE + e)], 1);
}

__global__ void k_isd() {
    int i = blockIdx.x * blockDim.x + threadIdx.x;
    if (i < NN) g_isd[i] = rsqrtf(1.0f + (float)g_cnt[i]);
}

__global__ void __launch_bounds__(1024) k_scan() {
    __shared__ int sh[2][1024];
    const int t  = threadIdx.x;
    const int CH = (NN + 1023) / 1024;   // 49
    const int b0 = t * CH;

    int local = 0;
    for (int i = 0; i < CH; i++) {
        int idx = b0 + i;
        if (idx < NN) local += g_cnt[idx];
    }
    int cur = 0;
    sh[cur][t] = local;
    __syncthreads();
    for (int off = 1; off < 1024; off <<= 1) {
        int nxt = cur ^ 1;
        int v = sh[cur][t];
        if (t >= off) v += sh[cur][t - off];
        sh[nxt][t] = v;
        __syncthreads();
        cur = nxt;
    }
    int run = (t == 0) ? 0 : sh[cur][t - 1];
    for (int i = 0; i < CH; i++) {
        int idx = b0 + i;
        if (idx < NN) { g_row[idx] = run; run += g_cnt[idx]; }
    }
}

__global__ void k_fill(const void* __restrict__ ei) {
    int e = blockIdx.x * blockDim.x + threadIdx.x;
    if (e >= NE) return;
    int s = edge_at(ei, e);
    int d = edge_at(ei, NE + e);
    int pos = g_row[d] + atomicAdd(&g_cur[d], 1);
    g_csr[pos] = s;
}

// ---------------- gather core (R6-exact): 2-way unroll, isd chain ------------
__device__ __forceinline__ float4 gather_rows(const float* __restrict__ h,
                                              int node, int lane, float sd,
                                              float4 acc) {
    const int beg = g_row[node];
    const int cnt = g_cnt[node];
    int e = 0;
    for (; e + 2 <= cnt; e += 2) {
        int s0 = g_csr[beg + e];
        int s1 = g_csr[beg + e + 1];
        float n0 = sd * g_isd[s0];
        float n1 = sd * g_isd[s1];
        float4 a = ((const float4*)(h + (size_t)s0 * 128))[lane];
        float4 b = ((const float4*)(h + (size_t)s1 * 128))[lane];
        acc.x += a.x * n0 + b.x * n1;
        acc.y += a.y * n0 + b.y * n1;
        acc.z += a.z * n0 + b.z * n1;
        acc.w += a.w * n0 + b.w * n1;
    }
    if (e < cnt) {
        int s0 = g_csr[beg + e];
        float n0 = sd * g_isd[s0];
        float4 a = ((const float4*)(h + (size_t)s0 * 128))[lane];
        acc.x += a.x * n0; acc.y += a.y * n0;
        acc.z += a.z * n0; acc.w += a.w * n0;
    }
    return acc;
}

// ---------------- aggregation 1: ax = A_norm @ x (128 feat) ------------------
__global__ void __launch_bounds__(256)
k_aggX(const float* __restrict__ x) {
    const int warp = threadIdx.x >> 5;
    const int lane = threadIdx.x & 31;
    const int node = blockIdx.x * 8 + warp;
    if (node >= NN) return;

    const float sd = g_isd[node];
    float4 t = ((const float4*)(x + (size_t)node * 128))[lane];
    const float w = sd * sd;
    float4 acc = make_float4(t.x * w, t.y * w, t.z * w, t.w * w);

    acc = gather_rows(x, node, lane, sd, acc);

    ((float4*)(g_ax + (size_t)node * 128))[lane] = acc;
}

// ---------------- tf32 tensor-core GEMM, cp.async double-buffered ------------
__device__ __forceinline__ uint32_t f2tf32(float f) {
    uint32_t o;
    asm("cvt.rna.tf32.f32 %0, %1;" : "=r"(o) : "f"(f));
    return o;
}

__device__ __forceinline__ void mma_tf32(float c[4], const uint32_t a[4],
                                         const uint32_t b[2]) {
    asm volatile(
        "mma.sync.aligned.m16n8k8.row.col.f32.tf32.tf32.f32 "
        "{%0,%1,%2,%3}, {%4,%5,%6,%7}, {%8,%9}, {%0,%1,%2,%3};"
        : "+f"(c[0]), "+f"(c[1]), "+f"(c[2]), "+f"(c[3])
        : "r"(a[0]), "r"(a[1]), "r"(a[2]), "r"(a[3]),
          "r"(b[0]), "r"(b[1]));
}

__device__ __forceinline__ void cp16(void* s, const void* g) {
    uint32_t sa = (uint32_t)__cvta_generic_to_shared(s);
    asm volatile("cp.async.cg.shared.global [%0], [%1], 16;"
                 :: "r"(sa), "l"(g) : "memory");
}

static constexpr int GBM = 128, GBN = 64, GBK = 32;
static constexpr int GLDA = GBK + 4;   // 36 floats: conflict-free frag loads
static constexpr int GLDB = GBN + 8;   // 72 floats
static constexpr int AS_SZ = GBM * GLDA;   // 4608 floats
static constexpr int BS_SZ = GBK * GLDB;   // 2304 floats
static constexpr int GEMM_SMEM = 2 * (AS_SZ + BS_SZ) * 4;   // 55296 B

template <bool L1>
__global__ void __launch_bounds__(256)
tgemm(const float* __restrict__ W, const float* __restrict__ bias) {
    constexpr int K  = L1 ? 128 : 256;
    constexpr int N  = L1 ? 256 : 128;
    constexpr int KT = K / GBK;

    const float* __restrict__ A = L1 ? g_ax : g_z1;
    float* __restrict__       C = L1 ? g_z1 : g_t2;

    extern __shared__ float smem[];
    float* As = smem;                   // [2][AS_SZ]
    float* Bs = smem + 2 * AS_SZ;       // [2][BS_SZ]

    const int tid  = threadIdx.x;
    const int lane = tid & 31;
    const int wid  = tid >> 5;
    const int wm   = wid & 3;
    const int wn   = wid >> 2;
    const int gID  = lane >> 2;
    const int tg   = lane & 3;

    const int bm0 = blockIdx.y * GBM;
    const int bn0 = blockIdx.x * GBN;

    float c[2][4][4] = {};

    auto stage = [&](int kt, int buf) {
        float* as = As + buf * AS_SZ;
        float* bs = Bs + buf * BS_SZ;
        #pragma unroll
        for (int i = 0; i < 4; i++) {           // A: 128x32 = 1024 float4
            int idx = tid + i * 256;
            int r   = idx >> 3;
            int c4  = (idx & 7) * 4;
            int rg  = min(bm0 + r, NN - 1);     // clamp: dup rows, never read
            cp16(&as[r * GLDA + c4], A + (size_t)rg * K + kt * GBK + c4);
        }
        #pragma unroll
        for (int i = 0; i < 2; i++) {           // B: 32x64 = 512 float4
            int idx = tid + i * 256;
            int r   = idx >> 4;
            int c4  = (idx & 15) * 4;
            cp16(&bs[r * GLDB + c4], W + (size_t)(kt * GBK + r) * N + bn0 + c4);
        }
        asm volatile("cp.async.commit_group;" ::: "memory");
    };

    stage(0, 0);
    for (int kt = 0; kt < KT; kt++) {
        int buf = kt & 1;
        if (kt + 1 < KT) {
            stage(kt + 1, buf ^ 1);
            asm volatile("cp.async.wait_group 1;" ::: "memory");
        } else {
            asm volatile("cp.async.wait_group 0;" ::: "memory");
        }
        __syncthreads();

        const float* as = As + buf * AS_SZ;
        const float* bs = Bs + buf * BS_SZ;
        #pragma unroll
        for (int kk = 0; kk < GBK / 8; kk++) {
            uint32_t a[2][4], b[4][2];
            #pragma unroll
            for (int mi = 0; mi < 2; mi++) {
                int rb = wm * 32 + mi * 16 + gID;
                int kb = kk * 8 + tg;
                a[mi][0] = f2tf32(as[rb * GLDA + kb]);
                a[mi][1] = f2tf32(as[(rb + 8) * GLDA + kb]);
                a[mi][2] = f2tf32(as[rb * GLDA + kb + 4]);
                a[mi][3] = f2tf32(as[(rb + 8) * GLDA + kb + 4]);
            }
            #pragma unroll
            for (int ni = 0; ni < 4; ni++) {
                int col = wn * 32 + ni * 8 + gID;
                int kb  = kk * 8 + tg;
                b[ni][0] = f2tf32(bs[kb * GLDB + col]);
                b[ni][1] = f2tf32(bs[(kb + 4) * GLDB + col]);
            }
            #pragma unroll
            for (int mi = 0; mi < 2; mi++)
                #pragma unroll
                for (int ni = 0; ni < 4; ni++)
                    mma_tf32(c[mi][ni], a[mi], b[ni]);
        }
        __syncthreads();
    }

    #pragma unroll
    for (int mi = 0; mi < 2; mi++) {
        int r0 = bm0 + wm * 32 + mi * 16 + gID;
        #pragma unroll
        for (int ni = 0; ni < 4; ni++) {
            int col = bn0 + wn * 32 + ni * 8 + tg * 2;
            float2 v0 = make_float2(c[mi][ni][0], c[mi][ni][1]);
            float2 v1 = make_float2(c[mi][ni][2], c[mi][ni][3]);
            if (L1) {
                float bx = bias[col], by = bias[col + 1];
                v0.x = fmaxf(v0.x + bx, 0.f); v0.y = fmaxf(v0.y + by, 0.f);
                v1.x = fmaxf(v1.x + bx, 0.f); v1.y = fmaxf(v1.y + by, 0.f);
            }
            if (r0 < NN)     *(float2*)(C + (size_t)r0 * N + col) = v0;
            if (r0 + 8 < NN) *(float2*)(C + (size_t)(r0 + 8) * N + col) = v1;
        }
    }
}

// ---------------- aggregation 2 + bias + relu + pool + fc --------------------
__global__ void __launch_bounds__(256)
k_agg2(const float* __restrict__ bias, const float* __restrict__ Wfc,
       float* __restrict__ out) {
    const int warp = threadIdx.x >> 5;
    const int lane = threadIdx.x & 31;
    const int node = blockIdx.x * 8 + warp;
    if (node >= NN) return;

    const float* __restrict__ h = g_t2;
    const float sd = g_isd[node];
    float4 t = ((const float4*)(h + (size_t)node * 128))[lane];
    const float w = sd * sd;
    float4 acc = make_float4(t.x * w, t.y * w, t.z * w, t.w * w);

    acc = gather_rows(h, node, lane, sd, acc);

    float4 bb = ((const float4*)bias)[lane];
    float4 wf = ((const float4*)Wfc)[lane];
    float dot =
        fmaxf(acc.x + bb.x, 0.f) * wf.x +
        fmaxf(acc.y + bb.y, 0.f) * wf.y +
        fmaxf(acc.z + bb.z, 0.f) * wf.z +
        fmaxf(acc.w + bb.w, 0.f) * wf.w;

    #pragma unroll
    for (int o = 16; o; o >>= 1) dot += __shfl_down_sync(0xffffffffu, dot, o);
    if (lane == 0) atomicAdd(out, dot * (1.0f / NN));
}

__global__ void k_out_init(const float* __restrict__ bfc, float* __restrict__ out) {
    out[0] = bfc[0];
}

// ---------------- launch ------------------------------------------------------
extern "C" void kernel_launch(void* const* d_in, const int* in_sizes, int n_in,
                              void* d_out, int out_size) {
    const float* x   = (const float*)d_in[0];
    const void*  ei  = d_in[1];                 // int32 or int64 — probed on device
    const float* W1  = (const float*)d_in[2];
    const float* b1  = (const float*)d_in[3];
    const float* W2  = (const float*)d_in[4];
    const float* b2  = (const float*)d_in[5];
    const float* Wfc = (const float*)d_in[6];
    const float* bfc = (const float*)d_in[7];
    float* out = (float*)d_out;
    (void)in_sizes; (void)n_in; (void)out_size;

    cudaFuncSetAttribute(tgemm<true>,
        cudaFuncAttributeMaxDynamicSharedMemorySize, GEMM_SMEM);
    cudaFuncSetAttribute(tgemm<false>,
        cudaFuncAttributeMaxDynamicSharedMemorySize, GEMM_SMEM);

    // dtype probe + CSR build (R6-exact)
    k_detect<<<1, 256>>>(ei);
    k_init  <<<(NN + 255) / 256, 256>>>();
    k_count <<<(NE + 255) / 256, 256>>>(ei);
    k_isd   <<<(NN + 255) / 256, 256>>>();
    k_scan  <<<1, 1024>>>();
    k_fill  <<<(NE + 255) / 256, 256>>>(ei);

    // layer 1: aggregate x first (narrower), then fused GEMM+bias+relu
    k_aggX<<<(NN + 7) / 8, 256>>>(x);
    tgemm<true><<<dim3(256 / 64, (NN + 127) / 128), 256, GEMM_SMEM>>>(W1, b1);

    // layer 2: transform first, then fused agg+bias+relu+pool+fc
    tgemm<false><<<dim3(128 / 64, (NN + 127) / 128), 256, GEMM_SMEM>>>(W2, nullptr);
    k_out_init<<<1, 1>>>(bfc, out);
    k_agg2<<<(NN + 7) / 8, 256>>>(b2, Wfc, out);
}